// round 8
// baseline (speedup 1.0000x reference)
#include <cuda_runtime.h>
#include <cuda_bf16.h>

// ---------------------------------------------------------------------------
// AdditiveAttention: B=4, LQ=LK=256, D=768
//   q = query@Wq + bq ; k = key@Wk + bk ; v = value@Wv + bv
//   scores[b,q,k] = sum_d Ws[d] * tanh(q[b,q,d] + k[b,k,d])   (+bs cancels in softmax)
//   weights = softmax_k(scores) ; attended = weights @ v
// Outputs: attended [4,256,768] then weights [4,256,256] (flattened, fp32)
// ---------------------------------------------------------------------------

#define B_ 4
#define L_ 256
#define D_ 768
#define M_ (B_ * L_)          // 1024 rows for projection GEMMs

// scratch (allocation-free rule: __device__ globals)
__device__ __align__(16) float g_qp[M_ * D_];
__device__ __align__(16) float g_kp[M_ * D_];
__device__ __align__(16) float g_vp[M_ * D_];
__device__ __align__(16) float g_w [B_ * L_ * L_];   // weights when out_w absent

// ---------------------------------------------------------------------------
// Kernel 1: projection GEMM, 128x128 tile, BK=8, 256 threads, 8x8 micro-tile.
// ---------------------------------------------------------------------------
__global__ __launch_bounds__(256, 2)
void proj_gemm_kernel(const float* __restrict__ Xq, const float* __restrict__ Xk,
                      const float* __restrict__ Xv,
                      const float* __restrict__ Wq, const float* __restrict__ bq,
                      const float* __restrict__ Wk, const float* __restrict__ bk,
                      const float* __restrict__ Wv, const float* __restrict__ bv)
{
    const int z = blockIdx.z;
    const float* X    = (z == 0) ? Xq : (z == 1) ? Xk : Xv;
    const float* W    = (z == 0) ? Wq : (z == 1) ? Wk : Wv;
    const float* bias = (z == 0) ? bq : (z == 1) ? bk : bv;
    float*       Y    = (z == 0) ? g_qp : (z == 1) ? g_kp : g_vp;

    __shared__ __align__(16) float As[2][8][128];
    __shared__ __align__(16) float Bs[2][8][128];

    const int tid = threadIdx.x;
    const int m0 = blockIdx.y * 128;
    const int n0 = blockIdx.x * 128;

    const int a_row = tid >> 1;
    const int a_col = (tid & 1) * 4;
    const int b_row = tid >> 5;
    const int b_col = (tid & 31) * 4;

    const float* Abase = X + (m0 + a_row) * D_ + a_col;
    const float* Bbase = W + b_row * D_ + n0 + b_col;

    const int NCHUNK = D_ / 8;   // 96

    float4 af = *(const float4*)(Abase);
    float4 bf = *(const float4*)(Bbase);

    int buf = 0;
    As[buf][a_col + 0][a_row] = af.x;
    As[buf][a_col + 1][a_row] = af.y;
    As[buf][a_col + 2][a_row] = af.z;
    As[buf][a_col + 3][a_row] = af.w;
    *(float4*)&Bs[buf][b_row][b_col] = bf;
    __syncthreads();

    const int tx = tid & 15;
    const int ty = tid >> 4;

    float acc[8][8];
    #pragma unroll
    for (int i = 0; i < 8; i++)
        #pragma unroll
        for (int j = 0; j < 8; j++) acc[i][j] = 0.f;

    for (int kt = 0; kt < NCHUNK; kt++) {
        float4 af_n, bf_n;
        if (kt + 1 < NCHUNK) {
            af_n = *(const float4*)(Abase + (kt + 1) * 8);
            bf_n = *(const float4*)(Bbase + (size_t)(kt + 1) * 8 * D_);
        }
        #pragma unroll
        for (int kk = 0; kk < 8; kk++) {
            float a_frag[8], b_frag[8];
            *(float4*)&a_frag[0] = *(const float4*)&As[buf][kk][ty * 8];
            *(float4*)&a_frag[4] = *(const float4*)&As[buf][kk][ty * 8 + 4];
            *(float4*)&b_frag[0] = *(const float4*)&Bs[buf][kk][tx * 8];
            *(float4*)&b_frag[4] = *(const float4*)&Bs[buf][kk][tx * 8 + 4];
            #pragma unroll
            for (int i = 0; i < 8; i++)
                #pragma unroll
                for (int j = 0; j < 8; j++)
                    acc[i][j] += a_frag[i] * b_frag[j];
        }
        if (kt + 1 < NCHUNK) {
            buf ^= 1;
            As[buf][a_col + 0][a_row] = af_n.x;
            As[buf][a_col + 1][a_row] = af_n.y;
            As[buf][a_col + 2][a_row] = af_n.z;
            As[buf][a_col + 3][a_row] = af_n.w;
            *(float4*)&Bs[buf][b_row][b_col] = bf_n;
            __syncthreads();
        }
    }

    float bv8[8];
    #pragma unroll
    for (int j = 0; j < 8; j++) bv8[j] = __ldg(bias + n0 + tx * 8 + j);

    #pragma unroll
    for (int i = 0; i < 8; i++) {
        float* yrow = Y + (size_t)(m0 + ty * 8 + i) * D_ + n0 + tx * 8;
        float4 o0, o1;
        o0.x = acc[i][0] + bv8[0]; o0.y = acc[i][1] + bv8[1];
        o0.z = acc[i][2] + bv8[2]; o0.w = acc[i][3] + bv8[3];
        o1.x = acc[i][4] + bv8[4]; o1.y = acc[i][5] + bv8[5];
        o1.z = acc[i][6] + bv8[6]; o1.w = acc[i][7] + bv8[7];
        *(float4*)(yrow)     = o0;
        *(float4*)(yrow + 4) = o1;
    }
}

// ---------------------------------------------------------------------------
// Kernel 2: scores (MUFU.TANH, scalar R5 loop) + softmax -> weights.
// D-SPLIT: 768 threads/CTA = (key, dslice of 3x256). AV phase removed.
// ---------------------------------------------------------------------------
#define TQ 4
#define DS_ (D_ / 3)          // 256 d's per slice

__device__ __forceinline__ float tanh_fast(float x) {
    float y;
    asm("tanh.approx.f32 %0, %1;" : "=f"(y) : "f"(x));
    return y;
}

__global__ __launch_bounds__(768, 2)
void scores_kernel(const float* __restrict__ Ws,
                   float* __restrict__ wbuf)      // weights destination
{
    __shared__ __align__(16) float sq[TQ][D_];        // 12 KB
    __shared__ __align__(16) float sws[D_];           //  3 KB
    __shared__ __align__(16) float spart[2][TQ][L_];  //  8 KB
    __shared__ __align__(16) float ssc[TQ][L_];       //  4 KB
    __shared__ float smax[TQ], sinv[TQ];

    const int tid = threadIdx.x;
    const int b  = blockIdx.x >> 6;
    const int q0 = (blockIdx.x & 63) * TQ;

    const int key = tid & 255;
    const int ds  = tid >> 8;          // 0..2

    const float4* qbase = (const float4*)(g_qp + (size_t)(b * L_ + q0) * D_);
    ((float4*)&sq[0][0])[tid] = qbase[tid];
    if (tid < D_ / 4)
        ((float4*)sws)[tid] = ((const float4*)Ws)[tid];
    __syncthreads();

    // ---- partial scores over this thread's 256-d slice (scalar, R5) ----
    const int dbase = ds * DS_;
    const float4* kb4 = (const float4*)(g_kp + ((size_t)b * L_ + key) * D_ + dbase);
    float acc[TQ];
    #pragma unroll
    for (int q = 0; q < TQ; q++) acc[q] = 0.f;

    float4 c0 = kb4[0], c1 = kb4[1];
    #pragma unroll 1
    for (int ch = 0; ch < DS_ / 8; ch++) {      // 32 chunks of 8
        float4 p0, p1;
        if (ch + 1 < DS_ / 8) {
            p0 = kb4[(ch + 1) * 2];
            p1 = kb4[(ch + 1) * 2 + 1];
        }
        const int d0 = dbase + ch * 8;
        const float4 w0 = *(const float4*)&sws[d0];
        const float4 w1 = *(const float4*)&sws[d0 + 4];
        #pragma unroll
        for (int q = 0; q < TQ; q++) {
            const float4 a0 = *(const float4*)&sq[q][d0];
            const float4 a1 = *(const float4*)&sq[q][d0 + 4];
            float s;
            s  = w0.x * tanh_fast(a0.x + c0.x);
            s += w0.y * tanh_fast(a0.y + c0.y);
            s += w0.z * tanh_fast(a0.z + c0.z);
            s += w0.w * tanh_fast(a0.w + c0.w);
            s += w1.x * tanh_fast(a1.x + c1.x);
            s += w1.y * tanh_fast(a1.y + c1.y);
            s += w1.z * tanh_fast(a1.z + c1.z);
            s += w1.w * tanh_fast(a1.w + c1.w);
            acc[q] += s;
        }
        c0 = p0; c1 = p1;
    }

    if (ds > 0) {
        #pragma unroll
        for (int q = 0; q < TQ; q++) spart[ds - 1][q][key] = acc[q];
    }
    __syncthreads();

    if (ds == 0) {
        #pragma unroll
        for (int q = 0; q < TQ; q++)
            ssc[q][key] = acc[q] + spart[0][q][key] + spart[1][q][key];
    }
    __syncthreads();

    const int w = tid >> 5, lane = tid & 31;
    if (w < TQ) {
        float m = -1e30f;
        #pragma unroll
        for (int j = 0; j < 8; j++) m = fmaxf(m, ssc[w][lane + j * 32]);
        #pragma unroll
        for (int o = 16; o > 0; o >>= 1) m = fmaxf(m, __shfl_xor_sync(0xffffffffu, m, o));
        float s = 0.f;
        #pragma unroll
        for (int j = 0; j < 8; j++) s += __expf(ssc[w][lane + j * 32] - m);
        #pragma unroll
        for (int o = 16; o > 0; o >>= 1) s += __shfl_xor_sync(0xffffffffu, s, o);
        if (lane == 0) { smax[w] = m; sinv[w] = 1.0f / s; }
    }
    __syncthreads();

    if (ds == 0) {
        #pragma unroll
        for (int q = 0; q < TQ; q++) {
            const float wt = __expf(ssc[q][key] - smax[q]) * sinv[q];
            wbuf[((size_t)(b * L_ + q0 + q)) * L_ + key] = wt;
        }
    }
}

// ---------------------------------------------------------------------------
// Kernel 3: attended = weights @ v   (per batch: [256q x 256k] x [256k x 768d])
// Tile 64q x 128d, BK=32, 256 threads, micro-tile 8q x 4d. grid = 96 CTAs.
// (Measured-correct in round 3; v traffic ~13MB vs ~196MB fused.)
// ---------------------------------------------------------------------------
__global__ __launch_bounds__(256, 2)
void av_kernel(const float* __restrict__ wsrc, float* __restrict__ out_att)
{
    __shared__ __align__(16) float w_s[32][64];    // [k][q]  8 KB
    __shared__ __align__(16) float v_s[32][128];   // [k][d] 16 KB

    const int tid = threadIdx.x;
    const int b  = blockIdx.z;
    const int q0 = blockIdx.y * 64;
    const int n0 = blockIdx.x * 128;

    const float* wbase = wsrc + ((size_t)(b * L_ + q0)) * L_;   // [64][256]
    const float* vbase = g_vp + (size_t)b * L_ * D_;            // [256][768]

    const int tx = tid & 31;   // d: 4 cols each
    const int ty = tid >> 5;   // q: 8 rows each

    float acc[8][4];
    #pragma unroll
    for (int i = 0; i < 8; i++)
        #pragma unroll
        for (int j = 0; j < 4; j++) acc[i][j] = 0.f;

    for (int k0 = 0; k0 < L_; k0 += 32) {
        {
            const int q = tid >> 2;            // 0..63
            const int kb = (tid & 3) * 8;      // 0,8,16,24
            const float4 wa = *(const float4*)(wbase + (size_t)q * L_ + k0 + kb);
            const float4 wb = *(const float4*)(wbase + (size_t)q * L_ + k0 + kb + 4);
            w_s[kb + 0][q] = wa.x; w_s[kb + 1][q] = wa.y;
            w_s[kb + 2][q] = wa.z; w_s[kb + 3][q] = wa.w;
            w_s[kb + 4][q] = wb.x; w_s[kb + 5][q] = wb.y;
            w_s[kb + 6][q] = wb.z; w_s[kb + 7][q] = wb.w;
        }
        #pragma unroll
        for (int r = 0; r < 4; r++) {
            const int idx = tid + r * 256;
            const int kk = idx >> 5;
            const int dd = (idx & 31) * 4;
            *(float4*)&v_s[kk][dd] =
                *(const float4*)(vbase + (size_t)(k0 + kk) * D_ + n0 + dd);
        }
        __syncthreads();

        #pragma unroll
        for (int kk = 0; kk < 32; kk++) {
            float a_frag[8], b_frag[4];
            *(float4*)&a_frag[0] = *(const float4*)&w_s[kk][ty * 8];
            *(float4*)&a_frag[4] = *(const float4*)&w_s[kk][ty * 8 + 4];
            *(float4*)&b_frag[0] = *(const float4*)&v_s[kk][tx * 4];
            #pragma unroll
            for (int i = 0; i < 8; i++)
                #pragma unroll
                for (int j = 0; j < 4; j++)
                    acc[i][j] += a_frag[i] * b_frag[j];
        }
        __syncthreads();
    }

    #pragma unroll
    for (int i = 0; i < 8; i++) {
        float* o = out_att + ((size_t)(b * L_ + q0 + ty * 8 + i)) * D_ + n0 + tx * 4;
        float4 ov;
        ov.x = acc[i][0]; ov.y = acc[i][1]; ov.z = acc[i][2]; ov.w = acc[i][3];
        *(float4*)o = ov;
    }
}

// ---------------------------------------------------------------------------
extern "C" void kernel_launch(void* const* d_in, const int* in_sizes, int n_in,
                              void* d_out, int out_size)
{
    const float* query = (const float*)d_in[0];
    const float* key   = (const float*)d_in[1];
    const float* value = (const float*)d_in[2];
    const float* Wq    = (const float*)d_in[3];
    const float* bq    = (const float*)d_in[4];
    const float* Wk    = (const float*)d_in[5];
    const float* bk    = (const float*)d_in[6];
    const float* Wv    = (const float*)d_in[7];
    const float* bv    = (const float*)d_in[8];
    const float* Ws    = (const float*)d_in[9];
    // d_in[10] = bs: constant shift inside softmax -> cancels; unused.

    float* out = (float*)d_out;
    const int ATT_N = B_ * L_ * D_;   // 786432
    const int W_N   = B_ * L_ * L_;   // 262144

    float* out_att = nullptr;
    float* out_w   = nullptr;
    if (out_size >= ATT_N + W_N) {
        out_att = out;
        out_w   = out + ATT_N;
    } else if (out_size == ATT_N) {
        out_att = out;
    } else {
        out_w = out;
    }

    // weights land directly in out_w when present; av reads from there
    float* wbuf = out_w ? out_w : g_w;

    dim3 ggrid(D_ / 128, M_ / 128, 3);        // (6, 8, 3) = 144 CTAs
    proj_gemm_kernel<<<ggrid, 256>>>(query, key, value, Wq, bq, Wk, bk, Wv, bv);

    scores_kernel<<<B_ * (L_ / TQ), 768>>>(Ws, wbuf);

    if (out_att) {
        dim3 agrid(D_ / 128, L_ / 64, B_);    // (6, 4, 4) = 96 CTAs
        av_kernel<<<agrid, 256>>>(wbuf, out_att);
    }
}

// round 9
// speedup vs baseline: 1.1593x; 1.1593x over previous
#include <cuda_runtime.h>
#include <cuda_bf16.h>
#include <mma.h>

using namespace nvcuda;

// ---------------------------------------------------------------------------
// AdditiveAttention: B=4, LQ=LK=256, D=768
//   q = query@Wq + bq ; k = key@Wk + bk ; v = value@Wv + bv
//   scores[b,q,k] = sum_d Ws[d] * tanh(q[b,q,d] + k[b,k,d])   (+bs cancels)
//   weights = softmax_k(scores) ; attended = weights @ v
// Projections on tensor cores via bf16 hi/lo split (3-term, fp32 accum).
// Biases: (bq+bk) folded into q-tile inside attn; bv added at output
// (softmax weights sum to 1). GEMMs therefore store raw X@W.
// ---------------------------------------------------------------------------

#define B_ 4
#define L_ 256
#define D_ 768
#define M_ (B_ * L_)          // 1024 rows per projection GEMM

// scratch (allocation-free rule: __device__ globals)
__device__ __align__(16) float g_qp[M_ * D_];
__device__ __align__(16) float g_kp[M_ * D_];
__device__ __align__(16) float g_vp[M_ * D_];
__device__ __align__(16) __nv_bfloat16 g_xhi[3][M_ * D_];
__device__ __align__(16) __nv_bfloat16 g_xlo[3][M_ * D_];
__device__ __align__(16) __nv_bfloat16 g_whi[3][D_ * D_];
__device__ __align__(16) __nv_bfloat16 g_wlo[3][D_ * D_];

// ---------------------------------------------------------------------------
// Split kernels: fp32 -> bf16 hi + bf16 lo  (x = hi + lo + O(2^-17 x))
// ---------------------------------------------------------------------------
__global__ __launch_bounds__(256)
void split_x_kernel(const float* __restrict__ q, const float* __restrict__ k,
                    const float* __restrict__ v)
{
    const int z = blockIdx.y;
    const float* src = (z == 0) ? q : (z == 1) ? k : v;
    const int i = blockIdx.x * 256 + threadIdx.x;
    if (i < M_ * D_) {
        const float x = src[i];
        const __nv_bfloat16 h = __float2bfloat16(x);
        g_xhi[z][i] = h;
        g_xlo[z][i] = __float2bfloat16(x - __bfloat162float(h));
    }
}

__global__ __launch_bounds__(256)
void split_w_kernel(const float* __restrict__ wq, const float* __restrict__ wk,
                    const float* __restrict__ wv)
{
    const int z = blockIdx.y;
    const float* src = (z == 0) ? wq : (z == 1) ? wk : wv;
    const int i = blockIdx.x * 256 + threadIdx.x;
    if (i < D_ * D_) {
        const float x = src[i];
        const __nv_bfloat16 h = __float2bfloat16(x);
        g_whi[z][i] = h;
        g_wlo[z][i] = __float2bfloat16(x - __bfloat162float(h));
    }
}

// ---------------------------------------------------------------------------
// Kernel 1: projection GEMM on tensor cores (wmma bf16, fp32 accum).
// Y = Xh@Wh + Xh@Wl + Xl@Wh      (lo*lo term ~2^-18 -> dropped)
// 128x128 tile, BK=16, 256 threads (8 warps, 4x2), warp tile 32x64.
// grid = (6, 8, 3) = 144 CTAs.
// ---------------------------------------------------------------------------
#define BM 128
#define BN 128
#define BKQ 16
#define BKP 24     // padded A smem stride (bf16 elems, mult of 8)
#define BNP 136    // padded B smem stride

__global__ __launch_bounds__(256, 1)
void proj_wmma_kernel()
{
    const int z = blockIdx.z;
    const __nv_bfloat16* __restrict__ Xh = g_xhi[z];
    const __nv_bfloat16* __restrict__ Xl = g_xlo[z];
    const __nv_bfloat16* __restrict__ Wh = g_whi[z];
    const __nv_bfloat16* __restrict__ Wl = g_wlo[z];
    float* Y = (z == 0) ? g_qp : (z == 1) ? g_kp : g_vp;

    __shared__ __align__(16) __nv_bfloat16 As[2][2][BM][BKP];   // [buf][h/l]
    __shared__ __align__(16) __nv_bfloat16 Bs[2][2][BKQ][BNP];

    const int tid = threadIdx.x;
    const int m0 = blockIdx.y * BM;
    const int n0 = blockIdx.x * BN;

    // A loader: 2 threads/row, 8 bf16 (uint4) each
    const int a_row = tid >> 1;
    const int a_col = (tid & 1) * 8;
    // B loader: 16 threads/row
    const int b_row = tid >> 4;
    const int b_col = (tid & 15) * 8;

    const __nv_bfloat16* Ah = Xh + (size_t)(m0 + a_row) * D_ + a_col;
    const __nv_bfloat16* Al = Xl + (size_t)(m0 + a_row) * D_ + a_col;
    const __nv_bfloat16* Bh = Wh + (size_t)b_row * D_ + n0 + b_col;
    const __nv_bfloat16* Bl = Wl + (size_t)b_row * D_ + n0 + b_col;

    const int NIT = D_ / BKQ;   // 48

    uint4 vah = *(const uint4*)Ah;
    uint4 val_ = *(const uint4*)Al;
    uint4 vbh = *(const uint4*)Bh;
    uint4 vbl = *(const uint4*)Bl;

    int buf = 0;
    *(uint4*)&As[buf][0][a_row][a_col] = vah;
    *(uint4*)&As[buf][1][a_row][a_col] = val_;
    *(uint4*)&Bs[buf][0][b_row][b_col] = vbh;
    *(uint4*)&Bs[buf][1][b_row][b_col] = vbl;
    __syncthreads();

    const int wid = tid >> 5;
    const int wr = wid >> 1;   // 0..3  (32 rows each)
    const int wc = wid & 1;    // 0..1  (64 cols each)

    wmma::fragment<wmma::accumulator, 16, 16, 16, float> acc[2][4];
    #pragma unroll
    for (int i = 0; i < 2; i++)
        #pragma unroll
        for (int j = 0; j < 4; j++) wmma::fill_fragment(acc[i][j], 0.0f);

    for (int kt = 0; kt < NIT; kt++) {
        uint4 nah, nal, nbh, nbl;
        if (kt + 1 < NIT) {
            nah = *(const uint4*)(Ah + (kt + 1) * BKQ);
            nal = *(const uint4*)(Al + (kt + 1) * BKQ);
            nbh = *(const uint4*)(Bh + (size_t)(kt + 1) * BKQ * D_);
            nbl = *(const uint4*)(Bl + (size_t)(kt + 1) * BKQ * D_);
        }

        wmma::fragment<wmma::matrix_a, 16, 16, 16, __nv_bfloat16, wmma::row_major> afh[2], afl[2];
        wmma::fragment<wmma::matrix_b, 16, 16, 16, __nv_bfloat16, wmma::row_major> bfh[4], bfl[4];
        #pragma unroll
        for (int i = 0; i < 2; i++) {
            wmma::load_matrix_sync(afh[i], &As[buf][0][wr * 32 + i * 16][0], BKP);
            wmma::load_matrix_sync(afl[i], &As[buf][1][wr * 32 + i * 16][0], BKP);
        }
        #pragma unroll
        for (int j = 0; j < 4; j++) {
            wmma::load_matrix_sync(bfh[j], &Bs[buf][0][0][wc * 64 + j * 16], BNP);
            wmma::load_matrix_sync(bfl[j], &Bs[buf][1][0][wc * 64 + j * 16], BNP);
        }
        #pragma unroll
        for (int i = 0; i < 2; i++)
            #pragma unroll
            for (int j = 0; j < 4; j++) {
                wmma::mma_sync(acc[i][j], afh[i], bfh[j], acc[i][j]);
                wmma::mma_sync(acc[i][j], afh[i], bfl[j], acc[i][j]);
                wmma::mma_sync(acc[i][j], afl[i], bfh[j], acc[i][j]);
            }

        if (kt + 1 < NIT) {
            buf ^= 1;
            *(uint4*)&As[buf][0][a_row][a_col] = nah;
            *(uint4*)&As[buf][1][a_row][a_col] = nal;
            *(uint4*)&Bs[buf][0][b_row][b_col] = nbh;
            *(uint4*)&Bs[buf][1][b_row][b_col] = nbl;
            __syncthreads();
        }
    }

    #pragma unroll
    for (int i = 0; i < 2; i++)
        #pragma unroll
        for (int j = 0; j < 4; j++)
            wmma::store_matrix_sync(
                Y + (size_t)(m0 + wr * 32 + i * 16) * D_ + n0 + wc * 64 + j * 16,
                acc[i][j], D_, wmma::mem_row_major);
}

// ---------------------------------------------------------------------------
// Kernel 2: fused scores + softmax + attended (R5 structure, best measured).
// Bias folds: sq[q][d] = qraw + bq[d] + bk[d];  out += bv[d].
// 768 threads/CTA = (key, dslice of 3x256); grid = 256 CTAs.
// ---------------------------------------------------------------------------
#define TQ 4
#define DS_ (D_ / 3)          // 256 d's per slice

__device__ __forceinline__ float tanh_fast(float x) {
    float y;
    asm("tanh.approx.f32 %0, %1;" : "=f"(y) : "f"(x));
    return y;
}

__global__ __launch_bounds__(768, 2)
void attn_kernel(const float* __restrict__ Ws,
                 const float* __restrict__ bq, const float* __restrict__ bk,
                 const float* __restrict__ bv,
                 float* __restrict__ out_att,   // may be null
                 float* __restrict__ out_w)     // may be null
{
    __shared__ __align__(16) float sq[TQ][D_];        // 12 KB
    __shared__ __align__(16) float sws[D_];           //  3 KB
    __shared__ __align__(16) float spart[2][TQ][L_];  //  8 KB
    __shared__ __align__(16) float ssc[TQ][L_];       //  4 KB
    __shared__ float smax[TQ], sinv[TQ];

    const int tid = threadIdx.x;
    const int b  = blockIdx.x >> 6;
    const int q0 = (blockIdx.x & 63) * TQ;

    const int key = tid & 255;
    const int ds  = tid >> 8;          // 0..2

    // load q tile with (bq+bk) folded in; one float4 per thread
    {
        const float4 qv = ((const float4*)(g_qp + (size_t)(b * L_ + q0) * D_))[tid];
        const int d4 = tid % (D_ / 4);                 // float4 index within row
        const float4 b1 = ((const float4*)bq)[d4];
        const float4 b2 = ((const float4*)bk)[d4];
        float4 o;
        o.x = qv.x + b1.x + b2.x;
        o.y = qv.y + b1.y + b2.y;
        o.z = qv.z + b1.z + b2.z;
        o.w = qv.w + b1.w + b2.w;
        ((float4*)&sq[0][0])[tid] = o;
    }
    if (tid < D_ / 4)
        ((float4*)sws)[tid] = ((const float4*)Ws)[tid];
    __syncthreads();

    // ---- partial scores over this thread's 256-d slice ----
    const int dbase = ds * DS_;
    const float4* kb4 = (const float4*)(g_kp + ((size_t)b * L_ + key) * D_ + dbase);
    float acc[TQ];
    #pragma unroll
    for (int q = 0; q < TQ; q++) acc[q] = 0.f;

    float4 c0 = kb4[0], c1 = kb4[1];
    #pragma unroll 1
    for (int ch = 0; ch < DS_ / 8; ch++) {      // 32 chunks of 8
        float4 p0, p1;
        if (ch + 1 < DS_ / 8) {
            p0 = kb4[(ch + 1) * 2];
            p1 = kb4[(ch + 1) * 2 + 1];
        }
        const int d0 = dbase + ch * 8;
        const float4 w0 = *(const float4*)&sws[d0];
        const float4 w1 = *(const float4*)&sws[d0 + 4];
        #pragma unroll
        for (int q = 0; q < TQ; q++) {
            const float4 a0 = *(const float4*)&sq[q][d0];
            const float4 a1 = *(const float4*)&sq[q][d0 + 4];
            float s;
            s  = w0.x * tanh_fast(a0.x + c0.x);
            s += w0.y * tanh_fast(a0.y + c0.y);
            s += w0.z * tanh_fast(a0.z + c0.z);
            s += w0.w * tanh_fast(a0.w + c0.w);
            s += w1.x * tanh_fast(a1.x + c1.x);
            s += w1.y * tanh_fast(a1.y + c1.y);
            s += w1.z * tanh_fast(a1.z + c1.z);
            s += w1.w * tanh_fast(a1.w + c1.w);
            acc[q] += s;
        }
        c0 = p0; c1 = p1;
    }

    if (ds > 0) {
        #pragma unroll
        for (int q = 0; q < TQ; q++) spart[ds - 1][q][key] = acc[q];
    }
    __syncthreads();

    if (ds == 0) {
        #pragma unroll
        for (int q = 0; q < TQ; q++)
            ssc[q][key] = acc[q] + spart[0][q][key] + spart[1][q][key];
    }
    __syncthreads();

    const int w = tid >> 5, lane = tid & 31;
    if (w < TQ) {
        float m = -1e30f;
        #pragma unroll
        for (int j = 0; j < 8; j++) m = fmaxf(m, ssc[w][lane + j * 32]);
        #pragma unroll
        for (int o = 16; o > 0; o >>= 1) m = fmaxf(m, __shfl_xor_sync(0xffffffffu, m, o));
        float s = 0.f;
        #pragma unroll
        for (int j = 0; j < 8; j++) s += __expf(ssc[w][lane + j * 32] - m);
        #pragma unroll
        for (int o = 16; o > 0; o >>= 1) s += __shfl_xor_sync(0xffffffffu, s, o);
        if (lane == 0) { smax[w] = m; sinv[w] = 1.0f / s; }
    }
    __syncthreads();

    if (ds == 0) {
        #pragma unroll
        for (int q = 0; q < TQ; q++) {
            const float wt = __expf(ssc[q][key] - smax[q]) * sinv[q];
            ssc[q][key] = wt;
            if (out_w)
                out_w[((size_t)(b * L_ + q0 + q)) * L_ + key] = wt;
        }
    }
    __syncthreads();

    // ---- attended: thread owns column tid (768 = D); +bv (weights sum to 1)
    if (out_att) {
        float a[TQ];
        #pragma unroll
        for (int q = 0; q < TQ; q++) a[q] = 0.f;
        const float* vcol = g_vp + (size_t)b * L_ * D_ + tid;
        #pragma unroll 1
        for (int kk = 0; kk < L_; kk += 4) {
            const float v0 = vcol[(size_t)(kk + 0) * D_];
            const float v1 = vcol[(size_t)(kk + 1) * D_];
            const float v2 = vcol[(size_t)(kk + 2) * D_];
            const float v3 = vcol[(size_t)(kk + 3) * D_];
            #pragma unroll
            for (int q = 0; q < TQ; q++) {
                const float4 wq = *(const float4*)&ssc[q][kk];
                a[q] += wq.x * v0 + wq.y * v1 + wq.z * v2 + wq.w * v3;
            }
        }
        const float bvt = bv[tid];
        #pragma unroll
        for (int q = 0; q < TQ; q++)
            out_att[((size_t)(b * L_ + q0 + q)) * D_ + tid] = a[q] + bvt;
    }
}

// ---------------------------------------------------------------------------
extern "C" void kernel_launch(void* const* d_in, const int* in_sizes, int n_in,
                              void* d_out, int out_size)
{
    const float* query = (const float*)d_in[0];
    const float* key   = (const float*)d_in[1];
    const float* value = (const float*)d_in[2];
    const float* Wq    = (const float*)d_in[3];
    const float* bq    = (const float*)d_in[4];
    const float* Wk    = (const float*)d_in[5];
    const float* bk    = (const float*)d_in[6];
    const float* Wv    = (const float*)d_in[7];
    const float* bv    = (const float*)d_in[8];
    const float* Ws    = (const float*)d_in[9];
    // d_in[10] = bs: constant shift inside softmax -> cancels; unused.

    float* out = (float*)d_out;
    const int ATT_N = B_ * L_ * D_;   // 786432
    const int W_N   = B_ * L_ * L_;   // 262144

    float* out_att = nullptr;
    float* out_w   = nullptr;
    if (out_size >= ATT_N + W_N) {            // both outputs, attended first
        out_att = out;
        out_w   = out + ATT_N;
    } else if (out_size == ATT_N) {           // attended only
        out_att = out;
    } else {                                   // weights only
        out_w = out;
    }

    // bf16 hi/lo splits
    split_x_kernel<<<dim3((M_ * D_ + 255) / 256, 3), 256>>>(query, key, value);
    split_w_kernel<<<dim3((D_ * D_ + 255) / 256, 3), 256>>>(Wq, Wk, Wv);

    // tensor-core projections (raw X@W; biases folded into attn)
    dim3 ggrid(D_ / BN, M_ / BM, 3);          // (6, 8, 3) = 144 CTAs
    proj_wmma_kernel<<<ggrid, 256>>>();

    attn_kernel<<<B_ * (L_ / TQ), 768>>>(Ws, bq, bk, bv, out_att, out_w);
}